// round 3
// baseline (speedup 1.0000x reference)
#include <cuda_runtime.h>
#include <math.h>

#define DMODEL 1024
#define NHEADS 16
#define DKK    64
#define SEQ    2048
#define NBATCH 2
#define NTOK   (NBATCH*SEQ)   // 4096

// Scratch (allocation-free rule: __device__ globals)
__device__ float g_Q[NTOK*DMODEL];   // head-major [B*H][S][64], pre-scaled by 1/8
__device__ float g_K[NTOK*DMODEL];   // head-major
__device__ float g_V[NTOK*DMODEL];   // head-major
__device__ float g_C[NTOK*DMODEL];  // context, token-major [T][1024]

// ---------------------------------------------------------------------------
// Kernel 1: fused QKV projection.  Out = X @ W^T  (NT gemm, both row-major)
// 128x128 tile, BK=8, 256 threads, 8x8 micro-tile (strided 16 for
// conflict-free smem reads). Stores permuted to head-major layout.
// ---------------------------------------------------------------------------
__global__ void __launch_bounds__(256)
proj_qkv_kernel(const float* __restrict__ X,
                const float* __restrict__ Wq,
                const float* __restrict__ Wk,
                const float* __restrict__ Wv)
{
    const int BM = 128, BN = 128, BK = 8;
    __shared__ float As[BK][BM];
    __shared__ float Bs[BK][BN];

    const float* W;
    float* Out;
    float scale;
    if (blockIdx.z == 0)      { W = Wq; Out = g_Q; scale = 0.125f; } // 1/sqrt(64)
    else if (blockIdx.z == 1) { W = Wk; Out = g_K; scale = 1.0f; }
    else                      { W = Wv; Out = g_V; scale = 1.0f; }

    const int tid  = threadIdx.x;
    const int row0 = blockIdx.x * BM;
    const int col0 = blockIdx.y * BN;

    const int lr = tid >> 1;          // 0..127 (tile row for loads)
    const int lc = (tid & 1) * 4;     // 0 or 4 (k offset for float4)

    const int tr = tid >> 4;          // 0..15 -> rows tr + i*16
    const int tc = tid & 15;          // 0..15 -> cols tc + j*16

    float acc[8][8];
#pragma unroll
    for (int i = 0; i < 8; i++)
#pragma unroll
        for (int j = 0; j < 8; j++) acc[i][j] = 0.f;

    for (int k0 = 0; k0 < DMODEL; k0 += BK) {
        float4 av = *reinterpret_cast<const float4*>(X + (size_t)(row0 + lr) * DMODEL + k0 + lc);
        float4 bv = *reinterpret_cast<const float4*>(W + (size_t)(col0 + lr) * DMODEL + k0 + lc);
        __syncthreads();
        As[lc + 0][lr] = av.x; As[lc + 1][lr] = av.y;
        As[lc + 2][lr] = av.z; As[lc + 3][lr] = av.w;
        Bs[lc + 0][lr] = bv.x; Bs[lc + 1][lr] = bv.y;
        Bs[lc + 2][lr] = bv.z; Bs[lc + 3][lr] = bv.w;
        __syncthreads();
#pragma unroll
        for (int k = 0; k < BK; k++) {
            float ra[8], rb[8];
#pragma unroll
            for (int i = 0; i < 8; i++) ra[i] = As[k][tr + i * 16];
#pragma unroll
            for (int j = 0; j < 8; j++) rb[j] = Bs[k][tc + j * 16];
#pragma unroll
            for (int i = 0; i < 8; i++)
#pragma unroll
                for (int j = 0; j < 8; j++) acc[i][j] += ra[i] * rb[j];
        }
    }

    // permuted store: token t=(b,s); column c=(h,d) -> Out[(b*H+h)][s][d]
#pragma unroll
    for (int i = 0; i < 8; i++) {
        int t = row0 + tr + i * 16;
        int b = t >> 11;           // /2048
        int s = t & 2047;
#pragma unroll
        for (int j = 0; j < 8; j++) {
            int c = col0 + tc + j * 16;
            int h = c >> 6;
            int d = c & 63;
            Out[(((size_t)(b * NHEADS + h)) * SEQ + s) * DKK + d] = acc[i][j] * scale;
        }
    }
}

// ---------------------------------------------------------------------------
// Kernel 2: flash attention (fp32).  One block = 64 q-rows of one (b,h).
// 256 threads, 4x4 micro-tiles.  Online softmax, stats in registers
// (replicated across the 16 lanes owning each row, kept in sync via
// xor-shuffle reductions).  P overlays the K smem buffer.
// ---------------------------------------------------------------------------
__global__ void __launch_bounds__(256)
flash_kernel()
{
    extern __shared__ float sm[];
    float* Qs = sm;                    // [64][64]  stride 64 (reads are ty-only -> broadcast)
    float* Ks = sm + 64 * 64;          // [64][65]  stride 65 (row-varying reads), reused as P
    float* Vs = Ks + 64 * 65;          // [64][65]

    const int tid = threadIdx.x;
    const int ty  = tid >> 4;          // 0..15 -> q rows 4*ty..4*ty+3
    const int tx  = tid & 15;          // 0..15 -> cols  4*tx..4*tx+3

    const int bh = blockIdx.y;         // b*16+h
    const int qb = blockIdx.x;

    const float* Qg = g_Q + (size_t)bh * SEQ * DKK + (size_t)qb * 64 * DKK;
    const float* Kg = g_K + (size_t)bh * SEQ * DKK;
    const float* Vg = g_V + (size_t)bh * SEQ * DKK;

    // load Q tile (4096 floats, 4 float4 per thread)
#pragma unroll
    for (int i = 0; i < 4; i++) {
        int f  = tid + i * 256;        // float4 index
        int r  = f >> 4;
        int c4 = (f & 15) * 4;
        *reinterpret_cast<float4*>(Qs + r * 64 + c4) =
            *reinterpret_cast<const float4*>(Qg + r * DKK + c4);
    }

    float rowm[4], rowl[4], oacc[4][4];
#pragma unroll
    for (int r = 0; r < 4; r++) {
        rowm[r] = -1e30f; rowl[r] = 0.f;
#pragma unroll
        for (int c = 0; c < 4; c++) oacc[r][c] = 0.f;
    }

    for (int kt = 0; kt < SEQ / 64; kt++) {
        __syncthreads();               // prev iter done reading Vs / P(Ks)
        const float* Kt = Kg + (size_t)kt * 64 * DKK;
        const float* Vt = Vg + (size_t)kt * 64 * DKK;
#pragma unroll
        for (int i = 0; i < 4; i++) {
            int f  = tid + i * 256;
            int r  = f >> 4;
            int c4 = (f & 15) * 4;
            float4 kv = *reinterpret_cast<const float4*>(Kt + r * DKK + c4);
            Ks[r * 65 + c4 + 0] = kv.x; Ks[r * 65 + c4 + 1] = kv.y;
            Ks[r * 65 + c4 + 2] = kv.z; Ks[r * 65 + c4 + 3] = kv.w;
            float4 vv = *reinterpret_cast<const float4*>(Vt + r * DKK + c4);
            Vs[r * 65 + c4 + 0] = vv.x; Vs[r * 65 + c4 + 1] = vv.y;
            Vs[r * 65 + c4 + 2] = vv.z; Vs[r * 65 + c4 + 3] = vv.w;
        }
        __syncthreads();

        // S = Q @ K^T  (Q pre-scaled)
        float s4[4][4];
#pragma unroll
        for (int r = 0; r < 4; r++)
#pragma unroll
            for (int c = 0; c < 4; c++) s4[r][c] = 0.f;
#pragma unroll 8
        for (int d = 0; d < DKK; d++) {
            float qa[4], kb[4];
#pragma unroll
            for (int r = 0; r < 4; r++) qa[r] = Qs[(ty * 4 + r) * 64 + d];
#pragma unroll
            for (int c = 0; c < 4; c++) kb[c] = Ks[(tx * 4 + c) * 65 + d];
#pragma unroll
            for (int r = 0; r < 4; r++)
#pragma unroll
                for (int c = 0; c < 4; c++) s4[r][c] += qa[r] * kb[c];
        }
        __syncthreads();               // everyone done reading Ks -> reuse as P

        // online softmax (row stats replicated across the 16 tx lanes)
#pragma unroll
        for (int r = 0; r < 4; r++) {
            float m = fmaxf(fmaxf(s4[r][0], s4[r][1]), fmaxf(s4[r][2], s4[r][3]));
#pragma unroll
            for (int off = 8; off > 0; off >>= 1)
                m = fmaxf(m, __shfl_xor_sync(0xffffffffu, m, off));
            float mnew = fmaxf(rowm[r], m);
            float sc   = __expf(rowm[r] - mnew);
            float lsum = 0.f;
#pragma unroll
            for (int c = 0; c < 4; c++) {
                float p = __expf(s4[r][c] - mnew);
                Ks[(ty * 4 + r) * 65 + tx * 4 + c] = p;   // P tile
                lsum += p;
            }
#pragma unroll
            for (int off = 8; off > 0; off >>= 1)
                lsum += __shfl_xor_sync(0xffffffffu, lsum, off);
            rowl[r] = rowl[r] * sc + lsum;
            rowm[r] = mnew;
#pragma unroll
            for (int c = 0; c < 4; c++) oacc[r][c] *= sc;
        }
        __syncthreads();               // P visible

        // O += P @ V
#pragma unroll 8
        for (int n = 0; n < 64; n++) {
            float pa[4], vb[4];
#pragma unroll
            for (int r = 0; r < 4; r++) pa[r] = Ks[(ty * 4 + r) * 65 + n];
#pragma unroll
            for (int c = 0; c < 4; c++) vb[c] = Vs[n * 65 + tx * 4 + c];
#pragma unroll
            for (int r = 0; r < 4; r++)
#pragma unroll
                for (int c = 0; c < 4; c++) oacc[r][c] += pa[r] * vb[c];
        }
    }

    // write context, token-major [T][1024] at column h*64 + d
    const int b = bh >> 4;
    const int h = bh & 15;
#pragma unroll
    for (int r = 0; r < 4; r++) {
        int q = qb * 64 + ty * 4 + r;
        float inv = 1.f / rowl[r];
        size_t base = ((size_t)(b * SEQ + q)) * DMODEL + h * DKK;
#pragma unroll
        for (int c = 0; c < 4; c++)
            g_C[base + tx * 4 + c] = oacc[r][c] * inv;
    }
}

// ---------------------------------------------------------------------------
// Kernel 3: output projection  out = C @ Wo^T + bo
// ---------------------------------------------------------------------------
__global__ void __launch_bounds__(256)
outproj_kernel(const float* __restrict__ Wo,
               const float* __restrict__ bo,
               float* __restrict__ out)
{
    const int BM = 128, BN = 128, BK = 8;
    __shared__ float As[BK][BM];
    __shared__ float Bs[BK][BN];

    const int tid  = threadIdx.x;
    const int row0 = blockIdx.x * BM;
    const int col0 = blockIdx.y * BN;

    const int lr = tid >> 1;
    const int lc = (tid & 1) * 4;
    const int tr = tid >> 4;
    const int tc = tid & 15;

    float acc[8][8];
#pragma unroll
    for (int i = 0; i < 8; i++)
#pragma unroll
        for (int j = 0; j < 8; j++) acc[i][j] = 0.f;

    for (int k0 = 0; k0 < DMODEL; k0 += BK) {
        float4 av = *reinterpret_cast<const float4*>(g_C + (size_t)(row0 + lr) * DMODEL + k0 + lc);
        float4 bv = *reinterpret_cast<const float4*>(Wo  + (size_t)(col0 + lr) * DMODEL + k0 + lc);
        __syncthreads();
        As[lc + 0][lr] = av.x; As[lc + 1][lr] = av.y;
        As[lc + 2][lr] = av.z; As[lc + 3][lr] = av.w;
        Bs[lc + 0][lr] = bv.x; Bs[lc + 1][lr] = bv.y;
        Bs[lc + 2][lr] = bv.z; Bs[lc + 3][lr] = bv.w;
        __syncthreads();
#pragma unroll
        for (int k = 0; k < BK; k++) {
            float ra[8], rb[8];
#pragma unroll
            for (int i = 0; i < 8; i++) ra[i] = As[k][tr + i * 16];
#pragma unroll
            for (int j = 0; j < 8; j++) rb[j] = Bs[k][tc + j * 16];
#pragma unroll
            for (int i = 0; i < 8; i++)
#pragma unroll
                for (int j = 0; j < 8; j++) acc[i][j] += ra[i] * rb[j];
        }
    }

#pragma unroll
    for (int i = 0; i < 8; i++) {
        int t = row0 + tr + i * 16;
#pragma unroll
        for (int j = 0; j < 8; j++) {
            int c = col0 + tc + j * 16;
            out[(size_t)t * DMODEL + c] = acc[i][j] + bo[c];
        }
    }
}

// ---------------------------------------------------------------------------
extern "C" void kernel_launch(void* const* d_in, const int* in_sizes, int n_in,
                              void* d_out, int out_size)
{
    (void)in_sizes; (void)n_in; (void)out_size;
    const float* x  = (const float*)d_in[0];
    const float* wq = (const float*)d_in[1];
    const float* wk = (const float*)d_in[2];
    const float* wv = (const float*)d_in[3];
    const float* wo = (const float*)d_in[4];
    const float* bo = (const float*)d_in[5];
    float* out = (float*)d_out;

    const int FSMEM = (64 * 64 + 2 * 64 * 65) * (int)sizeof(float); // 49664 B
    cudaFuncSetAttribute(flash_kernel, cudaFuncAttributeMaxDynamicSharedMemorySize, FSMEM);

    dim3 gproj(NTOK / 128, DMODEL / 128, 3);
    proj_qkv_kernel<<<gproj, 256>>>(x, wq, wk, wv);

    dim3 gf(SEQ / 64, NBATCH * NHEADS);
    flash_kernel<<<gf, 256, FSMEM>>>();

    dim3 go(NTOK / 128, DMODEL / 128);
    outproj_kernel<<<go, 256>>>(wo, bo, out);
}

// round 6
// speedup vs baseline: 1.4968x; 1.4968x over previous
#include <cuda_runtime.h>
#include <cuda_bf16.h>
#include <stdint.h>

#define DMODEL 1024
#define NHEADS 16
#define DKK    64
#define SEQ    2048
#define NBATCH 2
#define NTOK   (NBATCH*SEQ)   // 4096
#define WELEM  (DMODEL*DMODEL)

// ---------------- scratch (allocation-free rule: __device__ globals) --------
__device__ __nv_bfloat16 g_Xhi[NTOK*DMODEL], g_Xlo[NTOK*DMODEL];
__device__ __nv_bfloat16 g_Whi[4*WELEM],     g_Wlo[4*WELEM];     // q,k,v,o
__device__ float         g_Q[NTOK*DMODEL], g_K[NTOK*DMODEL], g_V[NTOK*DMODEL];
__device__ __nv_bfloat16 g_Chi[NTOK*DMODEL], g_Clo[NTOK*DMODEL]; // context

// ---------------- HMMA helpers (sm_80+ PTX, valid on plain compute_103) -----
__device__ __forceinline__ uint32_t smem_to_u32(const void* p) {
    uint32_t a;
    asm("{ .reg .u64 t; cvta.to.shared.u64 t, %1; cvt.u32.u64 %0, t; }" : "=r"(a) : "l"(p));
    return a;
}
__device__ __forceinline__ void ldsm4(uint32_t& r0, uint32_t& r1, uint32_t& r2,
                                      uint32_t& r3, uint32_t addr) {
    asm volatile("ldmatrix.sync.aligned.m8n8.x4.shared.b16 {%0,%1,%2,%3}, [%4];"
                 : "=r"(r0), "=r"(r1), "=r"(r2), "=r"(r3) : "r"(addr));
}
__device__ __forceinline__ void mma16816(float* d, const uint32_t* a, const uint32_t* b) {
    asm volatile("mma.sync.aligned.m16n8k16.row.col.f32.bf16.bf16.f32 "
                 "{%0,%1,%2,%3}, {%4,%5,%6,%7}, {%8,%9}, {%0,%1,%2,%3};"
                 : "+f"(d[0]), "+f"(d[1]), "+f"(d[2]), "+f"(d[3])
                 : "r"(a[0]), "r"(a[1]), "r"(a[2]), "r"(a[3]), "r"(b[0]), "r"(b[1]));
}

// ---------------- GEMM smem layout ------------------------------------------
// 4 tiles of [128 rows][64 bf16], padded row stride 72 bf16 (144B) so that
// ldmatrix's 8 row-reads land in disjoint bank groups (144 mod 128 = 16B shift)
#define TSTRIDE   72
#define TROWB     (TSTRIDE*2)        // 144 bytes
#define TILE_B    (128*TROWB)        // 18432 bytes
#define SA_HI     0
#define SA_LO     (TILE_B)
#define SB_HI     (2*TILE_B)
#define SB_LO     (3*TILE_B)
#define SM_TOTAL  (4*TILE_B)         // 73728 bytes
#define KCHUNK    64
#define NCHUNKS   (DMODEL / KCHUNK)  // 16

// ---------------------------------------------------------------------------
// Kernel 0: fp32 -> bf16 hi/lo split of X and the 4 weights.
// ---------------------------------------------------------------------------
__global__ void __launch_bounds__(256)
cvt_kernel(const float* __restrict__ x,
           const float* __restrict__ wq, const float* __restrict__ wk,
           const float* __restrict__ wv, const float* __restrict__ wo)
{
    int y = blockIdx.y;
    const float* src;
    __nv_bfloat16 *dh, *dl;
    int n4;
    if (y == 0) { src = x; dh = g_Xhi; dl = g_Xlo; n4 = NTOK*DMODEL/4; }
    else {
        src = (y == 1) ? wq : (y == 2) ? wk : (y == 3) ? wv : wo;
        size_t off = (size_t)(y - 1) * WELEM;
        dh = g_Whi + off; dl = g_Wlo + off; n4 = WELEM/4;
    }
    int i = blockIdx.x * blockDim.x + threadIdx.x;
    if (i >= n4) return;
    float4 v = reinterpret_cast<const float4*>(src)[i];
    float vv[4] = {v.x, v.y, v.z, v.w};
    uint32_t ph0 = 0, ph1 = 0, pl0 = 0, pl1 = 0;
#pragma unroll
    for (int j = 0; j < 4; j++) {
        __nv_bfloat16 h = __float2bfloat16(vv[j]);
        __nv_bfloat16 l = __float2bfloat16(vv[j] - __bfloat162float(h));
        uint32_t hb = (uint32_t)__bfloat16_as_ushort(h);
        uint32_t lb = (uint32_t)__bfloat16_as_ushort(l);
        if (j < 2) { ph0 |= hb << (16*j);     pl0 |= lb << (16*j); }
        else       { ph1 |= hb << (16*(j-2)); pl1 |= lb << (16*(j-2)); }
    }
    uint2 uh; uh.x = ph0; uh.y = ph1;
    uint2 ul; ul.x = pl0; ul.y = pl1;
    *reinterpret_cast<uint2*>(dh + 4*(size_t)i) = uh;
    *reinterpret_cast<uint2*>(dl + 4*(size_t)i) = ul;
}

// ---------------------------------------------------------------------------
// HMMA mainloop: acc[4][4][4] (fp32) = A[row0:+128][1024] @ B[col0:+128][1024]^T
// using bf16 hi/lo 3-term split. Warp tile 64x32: 2 warps in M x 4 in N.
// ---------------------------------------------------------------------------
__device__ __forceinline__ void gemm_mainloop_mma(
    const __nv_bfloat16* __restrict__ Ahi, const __nv_bfloat16* __restrict__ Alo,
    const __nv_bfloat16* __restrict__ Bhi, const __nv_bfloat16* __restrict__ Blo,
    int row0, int col0, char* smem, uint32_t smem_base,
    float acc[4][4][4])
{
    const int tid  = threadIdx.x;
    const int lane = tid & 31;
    const int wid  = tid >> 5;           // 0..7
    const int wm   = wid & 1;            // 2 warps in M
    const int wn   = wid >> 1;           // 4 warps in N

    // global->smem geometry: 4 x uint4 per tile per thread
    int so[4];
    size_t ga[4], gb[4];
#pragma unroll
    for (int i = 0; i < 4; i++) {
        int idx = tid + i * 256;
        int rr  = idx >> 3;              // 0..127
        int c16 = idx & 7;               // 16B chunk (8 bf16)
        so[i] = rr * TROWB + c16 * 16;
        ga[i] = (size_t)(row0 + rr) * DMODEL + c16 * 8;
        gb[i] = (size_t)(col0 + rr) * DMODEL + c16 * 8;
    }

    // ldmatrix per-lane addressing: row = base + (lane&15), +16B for lane>=16
    const uint32_t lrow  = (uint32_t)(lane & 15);
    const uint32_t lhalf = (uint32_t)((lane >> 4) * 16);

#pragma unroll
    for (int mi = 0; mi < 4; mi++)
#pragma unroll
        for (int ni = 0; ni < 4; ni++)
#pragma unroll
            for (int e = 0; e < 4; e++) acc[mi][ni][e] = 0.f;

    for (int kc = 0; kc < NCHUNKS; kc++) {
        const int k0 = kc * KCHUNK;
        uint4 vah[4], val[4], vbh[4], vbl[4];
#pragma unroll
        for (int i = 0; i < 4; i++) {
            vah[i] = *reinterpret_cast<const uint4*>(Ahi + ga[i] + k0);
            val[i] = *reinterpret_cast<const uint4*>(Alo + ga[i] + k0);
            vbh[i] = *reinterpret_cast<const uint4*>(Bhi + gb[i] + k0);
            vbl[i] = *reinterpret_cast<const uint4*>(Blo + gb[i] + k0);
        }
        __syncthreads();   // previous iteration's compute done
#pragma unroll
        for (int i = 0; i < 4; i++) {
            *reinterpret_cast<uint4*>(smem + SA_HI + so[i]) = vah[i];
            *reinterpret_cast<uint4*>(smem + SA_LO + so[i]) = val[i];
            *reinterpret_cast<uint4*>(smem + SB_HI + so[i]) = vbh[i];
            *reinterpret_cast<uint4*>(smem + SB_LO + so[i]) = vbl[i];
        }
        __syncthreads();

#pragma unroll
        for (int ks = 0; ks < 4; ks++) {        // 4 x k16 per chunk
            const uint32_t kb = ks * 32;        // byte offset of k16 within row

            // B fragments (hi & lo), n=32 -> 2 ldmatrix.x4 each
            uint32_t bh[4][2], bl[4][2];
#pragma unroll
            for (int half = 0; half < 2; half++) {
                uint32_t r0, r1, r2, r3;
                uint32_t baddr = smem_base + SB_HI +
                    (uint32_t)(wn * 32 + half * 16 + lrow) * TROWB + kb + lhalf;
                ldsm4(r0, r1, r2, r3, baddr);
                bh[half*2+0][0] = r0; bh[half*2+0][1] = r2;
                bh[half*2+1][0] = r1; bh[half*2+1][1] = r3;
                uint32_t laddr = baddr + (SB_LO - SB_HI);
                ldsm4(r0, r1, r2, r3, laddr);
                bl[half*2+0][0] = r0; bl[half*2+0][1] = r2;
                bl[half*2+1][0] = r1; bl[half*2+1][1] = r3;
            }

            // A_hi fragments, then hi*hi + hi*lo
            uint32_t af[4][4];
#pragma unroll
            for (int mi = 0; mi < 4; mi++) {
                uint32_t aaddr = smem_base + SA_HI +
                    (uint32_t)(wm * 64 + mi * 16 + lrow) * TROWB + kb + lhalf;
                ldsm4(af[mi][0], af[mi][1], af[mi][2], af[mi][3], aaddr);
            }
#pragma unroll
            for (int mi = 0; mi < 4; mi++)
#pragma unroll
                for (int ni = 0; ni < 4; ni++) {
                    mma16816(acc[mi][ni], af[mi], bh[ni]);
                    mma16816(acc[mi][ni], af[mi], bl[ni]);
                }

            // A_lo fragments (reuse regs), then lo*hi
#pragma unroll
            for (int mi = 0; mi < 4; mi++) {
                uint32_t aaddr = smem_base + SA_LO +
                    (uint32_t)(wm * 64 + mi * 16 + lrow) * TROWB + kb + lhalf;
                ldsm4(af[mi][0], af[mi][1], af[mi][2], af[mi][3], aaddr);
            }
#pragma unroll
            for (int mi = 0; mi < 4; mi++)
#pragma unroll
                for (int ni = 0; ni < 4; ni++)
                    mma16816(acc[mi][ni], af[mi], bh[ni]);
        }
    }
}

// ---------------------------------------------------------------------------
// Kernel 1: QKV projection (z selects weight), head-permuted fp32 store.
// ---------------------------------------------------------------------------
__global__ void __launch_bounds__(256, 2)
qkv_mma_kernel()
{
    extern __shared__ char smem[];
    uint32_t smem_base = smem_to_u32(smem);

    const int z = blockIdx.z;
    const int row0 = blockIdx.x * 128;
    const int col0 = blockIdx.y * 128;
    const __nv_bfloat16* Bh = g_Whi + (size_t)z * WELEM;
    const __nv_bfloat16* Bl = g_Wlo + (size_t)z * WELEM;

    float acc[4][4][4];
    gemm_mainloop_mma(g_Xhi, g_Xlo, Bh, Bl, row0, col0, smem, smem_base, acc);

    const float scale = (z == 0) ? 0.125f : 1.0f;   // fold 1/sqrt(64) into Q
    float* Out = (z == 0) ? g_Q : (z == 1) ? g_K : g_V;

    const int lane = threadIdx.x & 31;
    const int wid  = threadIdx.x >> 5;
    const int wm = wid & 1, wn = wid >> 1;
    const int lr = lane >> 2;            // 0..7
    const int lc = (lane & 3) * 2;       // 0,2,4,6

#pragma unroll
    for (int mi = 0; mi < 4; mi++)
#pragma unroll
        for (int ni = 0; ni < 4; ni++) {
            int c  = col0 + wn * 32 + ni * 8 + lc;
            int h  = c >> 6, d = c & 63;
#pragma unroll
            for (int half = 0; half < 2; half++) {
                int t = row0 + wm * 64 + mi * 16 + lr + half * 8;
                int b = t >> 11, s = t & 2047;
                float2 v;
                v.x = acc[mi][ni][half*2 + 0] * scale;
                v.y = acc[mi][ni][half*2 + 1] * scale;
                *reinterpret_cast<float2*>(
                    Out + (((size_t)(b * NHEADS + h)) * SEQ + s) * DKK + d) = v;
            }
        }
}

// ---------------------------------------------------------------------------
// Kernel 3: output projection  out = C @ Wo^T + bo  (C in split bf16)
// ---------------------------------------------------------------------------
__global__ void __launch_bounds__(256, 2)
outproj_mma_kernel(const float* __restrict__ bo, float* __restrict__ out)
{
    extern __shared__ char smem[];
    uint32_t smem_base = smem_to_u32(smem);

    const int row0 = blockIdx.x * 128;
    const int col0 = blockIdx.y * 128;

    float acc[4][4][4];
    gemm_mainloop_mma(g_Chi, g_Clo, g_Whi + (size_t)3 * WELEM, g_Wlo + (size_t)3 * WELEM,
                      row0, col0, smem, smem_base, acc);

    const int lane = threadIdx.x & 31;
    const int wid  = threadIdx.x >> 5;
    const int wm = wid & 1, wn = wid >> 1;
    const int lr = lane >> 2;
    const int lc = (lane & 3) * 2;

#pragma unroll
    for (int mi = 0; mi < 4; mi++)
#pragma unroll
        for (int ni = 0; ni < 4; ni++) {
            int c = col0 + wn * 32 + ni * 8 + lc;
            float2 bb = *reinterpret_cast<const float2*>(bo + c);
#pragma unroll
            for (int half = 0; half < 2; half++) {
                int t = row0 + wm * 64 + mi * 16 + lr + half * 8;
                float2 v;
                v.x = acc[mi][ni][half*2 + 0] + bb.x;
                v.y = acc[mi][ni][half*2 + 1] + bb.y;
                *reinterpret_cast<float2*>(out + (size_t)t * DMODEL + c) = v;
            }
        }
}

// ---------------------------------------------------------------------------
// Kernel 2: flash attention (fp32; epilogue emits split bf16 context).
// ---------------------------------------------------------------------------
__global__ void __launch_bounds__(256)
flash_kernel()
{
    extern __shared__ float sm[];
    float* Qs = sm;                    // [64][64]
    float* Ks = sm + 64 * 64;          // [64][65], reused as P
    float* Vs = Ks + 64 * 65;          // [64][65]

    const int tid = threadIdx.x;
    const int ty  = tid >> 4;
    const int tx  = tid & 15;

    const int bh = blockIdx.y;
    const int qb = blockIdx.x;

    const float* Qg = g_Q + (size_t)bh * SEQ * DKK + (size_t)qb * 64 * DKK;
    const float* Kg = g_K + (size_t)bh * SEQ * DKK;
    const float* Vg = g_V + (size_t)bh * SEQ * DKK;

#pragma unroll
    for (int i = 0; i < 4; i++) {
        int f  = tid + i * 256;
        int r  = f >> 4;
        int c4 = (f & 15) * 4;
        *reinterpret_cast<float4*>(Qs + r * 64 + c4) =
            *reinterpret_cast<const float4*>(Qg + r * DKK + c4);
    }

    float rowm[4], rowl[4], oacc[4][4];
#pragma unroll
    for (int r = 0; r < 4; r++) {
        rowm[r] = -1e30f; rowl[r] = 0.f;
#pragma unroll
        for (int c = 0; c < 4; c++) oacc[r][c] = 0.f;
    }

    for (int kt = 0; kt < SEQ / 64; kt++) {
        __syncthreads();
        const float* Kt = Kg + (size_t)kt * 64 * DKK;
        const float* Vt = Vg + (size_t)kt * 64 * DKK;
#pragma unroll
        for (int i = 0; i < 4; i++) {
            int f  = tid + i * 256;
            int r  = f >> 4;
            int c4 = (f & 15) * 4;
            float4 kv = *reinterpret_cast<const float4*>(Kt + r * DKK + c4);
            Ks[r * 65 + c4 + 0] = kv.x; Ks[r * 65 + c4 + 1] = kv.y;
            Ks[r * 65 + c4 + 2] = kv.z; Ks[r * 65 + c4 + 3] = kv.w;
            float4 vv = *reinterpret_cast<const float4*>(Vt + r * DKK + c4);
            Vs[r * 65 + c4 + 0] = vv.x; Vs[r * 65 + c4 + 1] = vv.y;
            Vs[r * 65 + c4 + 2] = vv.z; Vs[r * 65 + c4 + 3] = vv.w;
        }
        __syncthreads();

        float s4[4][4];
#pragma unroll
        for (int r = 0; r < 4; r++)
#pragma unroll
            for (int c = 0; c < 4; c++) s4[r][c] = 0.f;
#pragma unroll 8
        for (int d = 0; d < DKK; d++) {
            float qa[4], kb[4];
#pragma unroll
            for (int r = 0; r < 4; r++) qa[r] = Qs[(ty * 4 + r) * 64 + d];
#pragma unroll
            for (int c = 0; c < 4; c++) kb[c] = Ks[(tx * 4 + c) * 65 + d];
#pragma unroll
            for (int r = 0; r < 4; r++)
#pragma unroll
                for (int c = 0; c < 4; c++) s4[r][c] += qa[r] * kb[c];
        }
        __syncthreads();

#pragma unroll
        for (int r = 0; r < 4; r++) {
            float m = fmaxf(fmaxf(s4[r][0], s4[r][1]), fmaxf(s4[r][2], s4[r][3]));
#pragma unroll
            for (int off = 8; off > 0; off >>= 1)
                m = fmaxf(m, __shfl_xor_sync(0xffffffffu, m, off));
            float mnew = fmaxf(rowm[r], m);
            float sc   = __expf(rowm[r] - mnew);
            float lsum = 0.f;
#pragma unroll
            for (int c = 0; c < 4; c++) {
                float p = __expf(s4[r][c] - mnew);
                Ks[(ty * 4 + r) * 65 + tx * 4 + c] = p;
                lsum += p;
            }
#pragma unroll
            for (int off = 8; off > 0; off >>= 1)
                lsum += __shfl_xor_sync(0xffffffffu, lsum, off);
            rowl[r] = rowl[r] * sc + lsum;
            rowm[r] = mnew;
#pragma unroll
            for (int c = 0; c < 4; c++) oacc[r][c] *= sc;
        }
        __syncthreads();

#pragma unroll 8
        for (int n = 0; n < 64; n++) {
            float pa[4], vb[4];
#pragma unroll
            for (int r = 0; r < 4; r++) pa[r] = Ks[(ty * 4 + r) * 65 + n];
#pragma unroll
            for (int c = 0; c < 4; c++) vb[c] = Vs[n * 65 + tx * 4 + c];
#pragma unroll
            for (int r = 0; r < 4; r++)
#pragma unroll
                for (int c = 0; c < 4; c++) oacc[r][c] += pa[r] * vb[c];
        }
    }

    // epilogue: context -> split bf16 (hi/lo), token-major [T][1024]
    const int b = bh >> 4;
    const int h = bh & 15;
#pragma unroll
    for (int r = 0; r < 4; r++) {
        int q = qb * 64 + ty * 4 + r;
        float inv = 1.f / rowl[r];
        size_t base = ((size_t)(b * SEQ + q)) * DMODEL + h * DKK + tx * 4;
        uint32_t ph0 = 0, ph1 = 0, pl0 = 0, pl1 = 0;
#pragma unroll
        for (int c = 0; c < 4; c++) {
            float v = oacc[r][c] * inv;
            __nv_bfloat16 hi = __float2bfloat16(v);
            __nv_bfloat16 lo = __float2bfloat16(v - __bfloat162float(hi));
            uint32_t hb = (uint32_t)__bfloat16_as_ushort(hi);
            uint32_t lb = (uint32_t)__bfloat16_as_ushort(lo);
            if (c < 2) { ph0 |= hb << (16*c);     pl0 |= lb << (16*c); }
            else       { ph1 |= hb << (16*(c-2)); pl1 |= lb << (16*(c-2)); }
        }
        uint2 uh; uh.x = ph0; uh.y = ph1;
        uint2 ul; ul.x = pl0; ul.y = pl1;
        *reinterpret_cast<uint2*>(g_Chi + base) = uh;
        *reinterpret_cast<uint2*>(g_Clo + base) = ul;
    }
}

// ---------------------------------------------------------------------------
extern "C" void kernel_launch(void* const* d_in, const int* in_sizes, int n_in,
                              void* d_out, int out_size)
{
    (void)in_sizes; (void)n_in; (void)out_size;
    const float* x  = (const float*)d_in[0];
    const float* wq = (const float*)d_in[1];
    const float* wk = (const float*)d_in[2];
    const float* wv = (const float*)d_in[3];
    const float* wo = (const float*)d_in[4];
    const float* bo = (const float*)d_in[5];
    float* out = (float*)d_out;

    const int FSMEM = (64 * 64 + 2 * 64 * 65) * (int)sizeof(float); // 49664 B
    cudaFuncSetAttribute(flash_kernel, cudaFuncAttributeMaxDynamicSharedMemorySize, FSMEM);
    cudaFuncSetAttribute(qkv_mma_kernel, cudaFuncAttributeMaxDynamicSharedMemorySize, SM_TOTAL);
    cudaFuncSetAttribute(outproj_mma_kernel, cudaFuncAttributeMaxDynamicSharedMemorySize, SM_TOTAL);

    // 0) split-convert X and all weights to bf16 hi/lo
    cvt_kernel<<<dim3(4096, 5), 256>>>(x, wq, wk, wv, wo);

    // 1) QKV projections on HMMA tensor cores (head-permuted fp32 outputs)
    qkv_mma_kernel<<<dim3(NTOK / 128, DMODEL / 128, 3), 256, SM_TOTAL>>>();

    // 2) flash attention (fp32), emits split-bf16 context
    flash_kernel<<<dim3(SEQ / 64, NBATCH * NHEADS), 256, FSMEM>>>();

    // 3) output projection on HMMA tensor cores + bias
    outproj_mma_kernel<<<dim3(NTOK / 128, DMODEL / 128), 256, SM_TOTAL>>>(bo, out);
}

// round 8
// speedup vs baseline: 2.9277x; 1.9559x over previous
#include <cuda_runtime.h>
#include <cuda_bf16.h>
#include <stdint.h>

#define DMODEL 1024
#define NHEADS 16
#define DKK    64
#define SEQ    2048
#define NBATCH 2
#define NTOK   (NBATCH*SEQ)   // 4096
#define WELEM  (DMODEL*DMODEL)

// ---------------- scratch (allocation-free rule: __device__ globals) --------
__device__ __nv_bfloat16 g_Xhi[NTOK*DMODEL], g_Xlo[NTOK*DMODEL];
__device__ __nv_bfloat16 g_Whi[4*WELEM],     g_Wlo[4*WELEM];     // q,k,v,o
__device__ __nv_bfloat16 g_Qhi[NTOK*DMODEL], g_Qlo[NTOK*DMODEL]; // head-major
__device__ __nv_bfloat16 g_Khi[NTOK*DMODEL], g_Klo[NTOK*DMODEL];
__device__ __nv_bfloat16 g_Vhi[NTOK*DMODEL], g_Vlo[NTOK*DMODEL];
__device__ __nv_bfloat16 g_Chi[NTOK*DMODEL], g_Clo[NTOK*DMODEL]; // context

// ---------------- HMMA helpers (sm_80+ PTX, valid on plain compute_103) -----
__device__ __forceinline__ uint32_t smem_to_u32(const void* p) {
    uint32_t a;
    asm("{ .reg .u64 t; cvta.to.shared.u64 t, %1; cvt.u32.u64 %0, t; }" : "=r"(a) : "l"(p));
    return a;
}
__device__ __forceinline__ void ldsm4(uint32_t& r0, uint32_t& r1, uint32_t& r2,
                                      uint32_t& r3, uint32_t addr) {
    asm volatile("ldmatrix.sync.aligned.m8n8.x4.shared.b16 {%0,%1,%2,%3}, [%4];"
                 : "=r"(r0), "=r"(r1), "=r"(r2), "=r"(r3) : "r"(addr));
}
__device__ __forceinline__ void ldsm4t(uint32_t& r0, uint32_t& r1, uint32_t& r2,
                                       uint32_t& r3, uint32_t addr) {
    asm volatile("ldmatrix.sync.aligned.m8n8.x4.trans.shared.b16 {%0,%1,%2,%3}, [%4];"
                 : "=r"(r0), "=r"(r1), "=r"(r2), "=r"(r3) : "r"(addr));
}
__device__ __forceinline__ void mma16816(float* d, const uint32_t* a, const uint32_t* b) {
    asm volatile("mma.sync.aligned.m16n8k16.row.col.f32.bf16.bf16.f32 "
                 "{%0,%1,%2,%3}, {%4,%5,%6,%7}, {%8,%9}, {%0,%1,%2,%3};"
                 : "+f"(d[0]), "+f"(d[1]), "+f"(d[2]), "+f"(d[3])
                 : "r"(a[0]), "r"(a[1]), "r"(a[2]), "r"(a[3]), "r"(b[0]), "r"(b[1]));
}
// split two floats into packed bf16 hi pair + lo pair
__device__ __forceinline__ void split2(float a, float b, uint32_t& hi, uint32_t& lo) {
    __nv_bfloat16 ah = __float2bfloat16(a), bh = __float2bfloat16(b);
    __nv_bfloat16 al = __float2bfloat16(a - __bfloat162float(ah));
    __nv_bfloat16 bl = __float2bfloat16(b - __bfloat162float(bh));
    hi = ((uint32_t)__bfloat16_as_ushort(bh) << 16) | (uint32_t)__bfloat16_as_ushort(ah);
    lo = ((uint32_t)__bfloat16_as_ushort(bl) << 16) | (uint32_t)__bfloat16_as_ushort(al);
}

// ---------------- GEMM smem layout ------------------------------------------
#define TSTRIDE   72
#define TROWB     (TSTRIDE*2)        // 144 bytes, conflict-free ldmatrix stride
#define TILE_B    (128*TROWB)        // 18432 bytes
#define SA_HI     0
#define SA_LO     (TILE_B)
#define SB_HI     (2*TILE_B)
#define SB_LO     (3*TILE_B)
#define SM_TOTAL  (4*TILE_B)         // 73728 bytes
#define KCHUNK    64
#define NCHUNKS   (DMODEL / KCHUNK)  // 16

// ---------------- flash smem layout -----------------------------------------
#define KVTILE_B  (64*TROWB)         // 9216
#define SQ_HI     0
#define SQ_LO     18432
#define SK_HI_F   36864
#define SK_LO_F   46080
#define SV_HI_F   55296
#define SV_LO_F   64512
#define FSMEM     73728

// ---------------------------------------------------------------------------
// Kernel 0: fp32 -> bf16 hi/lo split of X and the 4 weights.
// ---------------------------------------------------------------------------
__global__ void __launch_bounds__(256)
cvt_kernel(const float* __restrict__ x,
           const float* __restrict__ wq, const float* __restrict__ wk,
           const float* __restrict__ wv, const float* __restrict__ wo)
{
    int y = blockIdx.y;
    const float* src;
    __nv_bfloat16 *dh, *dl;
    int n4;
    if (y == 0) { src = x; dh = g_Xhi; dl = g_Xlo; n4 = NTOK*DMODEL/4; }
    else {
        src = (y == 1) ? wq : (y == 2) ? wk : (y == 3) ? wv : wo;
        size_t off = (size_t)(y - 1) * WELEM;
        dh = g_Whi + off; dl = g_Wlo + off; n4 = WELEM/4;
    }
    int i = blockIdx.x * blockDim.x + threadIdx.x;
    if (i >= n4) return;
    float4 v = reinterpret_cast<const float4*>(src)[i];
    uint32_t h0, l0, h1, l1;
    split2(v.x, v.y, h0, l0);
    split2(v.z, v.w, h1, l1);
    uint2 uh; uh.x = h0; uh.y = h1;
    uint2 ul; ul.x = l0; ul.y = l1;
    *reinterpret_cast<uint2*>(dh + 4*(size_t)i) = uh;
    *reinterpret_cast<uint2*>(dl + 4*(size_t)i) = ul;
}

// ---------------------------------------------------------------------------
// HMMA mainloop: acc[4][4][4] = A[row0:+128][1024] @ B[col0:+128][1024]^T
// (bf16 hi/lo 3-term split; warp tile 64x32: 2 warps in M x 4 in N)
// ---------------------------------------------------------------------------
__device__ __forceinline__ void gemm_mainloop_mma(
    const __nv_bfloat16* __restrict__ Ahi, const __nv_bfloat16* __restrict__ Alo,
    const __nv_bfloat16* __restrict__ Bhi, const __nv_bfloat16* __restrict__ Blo,
    int row0, int col0, char* smem, uint32_t smem_base,
    float acc[4][4][4])
{
    const int tid  = threadIdx.x;
    const int lane = tid & 31;
    const int wid  = tid >> 5;
    const int wm   = wid & 1;
    const int wn   = wid >> 1;

    int so[4];
    size_t ga[4], gb[4];
#pragma unroll
    for (int i = 0; i < 4; i++) {
        int idx = tid + i * 256;
        int rr  = idx >> 3;
        int c16 = idx & 7;
        so[i] = rr * TROWB + c16 * 16;
        ga[i] = (size_t)(row0 + rr) * DMODEL + c16 * 8;
        gb[i] = (size_t)(col0 + rr) * DMODEL + c16 * 8;
    }

    const uint32_t lrow  = (uint32_t)(lane & 15);
    const uint32_t lhalf = (uint32_t)((lane >> 4) * 16);

#pragma unroll
    for (int mi = 0; mi < 4; mi++)
#pragma unroll
        for (int ni = 0; ni < 4; ni++)
#pragma unroll
            for (int e = 0; e < 4; e++) acc[mi][ni][e] = 0.f;

    for (int kc = 0; kc < NCHUNKS; kc++) {
        const int k0 = kc * KCHUNK;
        uint4 vah[4], val[4], vbh[4], vbl[4];
#pragma unroll
        for (int i = 0; i < 4; i++) {
            vah[i] = *reinterpret_cast<const uint4*>(Ahi + ga[i] + k0);
            val[i] = *reinterpret_cast<const uint4*>(Alo + ga[i] + k0);
            vbh[i] = *reinterpret_cast<const uint4*>(Bhi + gb[i] + k0);
            vbl[i] = *reinterpret_cast<const uint4*>(Blo + gb[i] + k0);
        }
        __syncthreads();
#pragma unroll
        for (int i = 0; i < 4; i++) {
            *reinterpret_cast<uint4*>(smem + SA_HI + so[i]) = vah[i];
            *reinterpret_cast<uint4*>(smem + SA_LO + so[i]) = val[i];
            *reinterpret_cast<uint4*>(smem + SB_HI + so[i]) = vbh[i];
            *reinterpret_cast<uint4*>(smem + SB_LO + so[i]) = vbl[i];
        }
        __syncthreads();

#pragma unroll
        for (int ks = 0; ks < 4; ks++) {
            const uint32_t kb = ks * 32;
            uint32_t bhf[4][2], blf[4][2];
#pragma unroll
            for (int half = 0; half < 2; half++) {
                uint32_t r0, r1, r2, r3;
                uint32_t baddr = smem_base + SB_HI +
                    (uint32_t)(wn * 32 + half * 16 + lrow) * TROWB + kb + lhalf;
                ldsm4(r0, r1, r2, r3, baddr);
                bhf[half*2+0][0] = r0; bhf[half*2+0][1] = r2;
                bhf[half*2+1][0] = r1; bhf[half*2+1][1] = r3;
                ldsm4(r0, r1, r2, r3, baddr + (SB_LO - SB_HI));
                blf[half*2+0][0] = r0; blf[half*2+0][1] = r2;
                blf[half*2+1][0] = r1; blf[half*2+1][1] = r3;
            }
            uint32_t af[4][4];
#pragma unroll
            for (int mi = 0; mi < 4; mi++) {
                uint32_t aaddr = smem_base + SA_HI +
                    (uint32_t)(wm * 64 + mi * 16 + lrow) * TROWB + kb + lhalf;
                ldsm4(af[mi][0], af[mi][1], af[mi][2], af[mi][3], aaddr);
            }
#pragma unroll
            for (int mi = 0; mi < 4; mi++)
#pragma unroll
                for (int ni = 0; ni < 4; ni++) {
                    mma16816(acc[mi][ni], af[mi], bhf[ni]);
                    mma16816(acc[mi][ni], af[mi], blf[ni]);
                }
#pragma unroll
            for (int mi = 0; mi < 4; mi++) {
                uint32_t aaddr = smem_base + SA_LO +
                    (uint32_t)(wm * 64 + mi * 16 + lrow) * TROWB + kb + lhalf;
                ldsm4(af[mi][0], af[mi][1], af[mi][2], af[mi][3], aaddr);
            }
#pragma unroll
            for (int mi = 0; mi < 4; mi++)
#pragma unroll
                for (int ni = 0; ni < 4; ni++)
                    mma16816(acc[mi][ni], af[mi], bhf[ni]);
        }
    }
}

// ---------------------------------------------------------------------------
// Kernel 1: QKV projection; epilogue stores head-major bf16 hi/lo.
// ---------------------------------------------------------------------------
__global__ void __launch_bounds__(256, 2)
qkv_mma_kernel()
{
    extern __shared__ char smem[];
    uint32_t smem_base = smem_to_u32(smem);

    const int z = blockIdx.z;
    const int row0 = blockIdx.x * 128;
    const int col0 = blockIdx.y * 128;
    const __nv_bfloat16* Bh = g_Whi + (size_t)z * WELEM;
    const __nv_bfloat16* Bl = g_Wlo + (size_t)z * WELEM;

    float acc[4][4][4];
    gemm_mainloop_mma(g_Xhi, g_Xlo, Bh, Bl, row0, col0, smem, smem_base, acc);

    const float scale = (z == 0) ? 0.125f : 1.0f;   // 1/sqrt(64) folded into Q
    __nv_bfloat16* Ohi = (z == 0) ? g_Qhi : (z == 1) ? g_Khi : g_Vhi;
    __nv_bfloat16* Olo = (z == 0) ? g_Qlo : (z == 1) ? g_Klo : g_Vlo;

    const int lane = threadIdx.x & 31;
    const int wid  = threadIdx.x >> 5;
    const int wm = wid & 1, wn = wid >> 1;
    const int lr = lane >> 2;
    const int lc = (lane & 3) * 2;

#pragma unroll
    for (int mi = 0; mi < 4; mi++)
#pragma unroll
        for (int ni = 0; ni < 4; ni++) {
            int c = col0 + wn * 32 + ni * 8 + lc;
            int h = c >> 6, d = c & 63;
#pragma unroll
            for (int half = 0; half < 2; half++) {
                int t = row0 + wm * 64 + mi * 16 + lr + half * 8;
                int b = t >> 11, s = t & 2047;
                uint32_t hi, lo;
                split2(acc[mi][ni][half*2] * scale, acc[mi][ni][half*2+1] * scale, hi, lo);
                size_t o = (((size_t)(b * NHEADS + h)) * SEQ + s) * DKK + d;
                *reinterpret_cast<uint32_t*>(Ohi + o) = hi;
                *reinterpret_cast<uint32_t*>(Olo + o) = lo;
            }
        }
}

// ---------------------------------------------------------------------------
// Kernel 3: output projection  out = C @ Wo^T + bo
// ---------------------------------------------------------------------------
__global__ void __launch_bounds__(256, 2)
outproj_mma_kernel(const float* __restrict__ bo, float* __restrict__ out)
{
    extern __shared__ char smem[];
    uint32_t smem_base = smem_to_u32(smem);

    const int row0 = blockIdx.x * 128;
    const int col0 = blockIdx.y * 128;

    float acc[4][4][4];
    gemm_mainloop_mma(g_Chi, g_Clo, g_Whi + (size_t)3 * WELEM, g_Wlo + (size_t)3 * WELEM,
                      row0, col0, smem, smem_base, acc);

    const int lane = threadIdx.x & 31;
    const int wid  = threadIdx.x >> 5;
    const int wm = wid & 1, wn = wid >> 1;
    const int lr = lane >> 2;
    const int lc = (lane & 3) * 2;

#pragma unroll
    for (int mi = 0; mi < 4; mi++)
#pragma unroll
        for (int ni = 0; ni < 4; ni++) {
            int c = col0 + wn * 32 + ni * 8 + lc;
            float2 bb = *reinterpret_cast<const float2*>(bo + c);
#pragma unroll
            for (int half = 0; half < 2; half++) {
                int t = row0 + wm * 64 + mi * 16 + lr + half * 8;
                float2 v;
                v.x = acc[mi][ni][half*2 + 0] + bb.x;
                v.y = acc[mi][ni][half*2 + 1] + bb.y;
                *reinterpret_cast<float2*>(out + (size_t)t * DMODEL + c) = v;
            }
        }
}

// ---------------------------------------------------------------------------
// Kernel 2: flash attention on HMMA tensor cores (bf16 hi/lo, 3-term).
// CTA: 128 q-rows of one (b,h); 8 warps, each m16 x full 64 kv / 64 d.
// ---------------------------------------------------------------------------
__global__ void __launch_bounds__(256, 2)
flash_mma_kernel()
{
    extern __shared__ char smem[];
    uint32_t sb = smem_to_u32(smem);
    const int tid  = threadIdx.x;
    const int lane = tid & 31;
    const int wq   = tid >> 5;
    const int bh   = blockIdx.y;
    const int qb   = blockIdx.x;
    const int b    = bh >> 4, h = bh & 15;

    const uint32_t lrow  = (uint32_t)(lane & 15);
    const uint32_t lhalf = (uint32_t)((lane >> 4) * 16);
    // V trans-ldmatrix lane addressing
    const uint32_t vrow  = (uint32_t)((lane & 7) + ((lane >> 4) & 1) * 8);
    const uint32_t vcol  = (uint32_t)(((lane >> 3) & 1) * 8);

    const size_t qoff  = ((size_t)bh * SEQ + (size_t)qb * 128) * DKK;
    const size_t kvoff = (size_t)bh * SEQ * DKK;

    // load Q tile (128x64 hi/lo)
#pragma unroll
    for (int i = 0; i < 4; i++) {
        int idx = tid + i * 256;
        int rr = idx >> 3, c16 = idx & 7;
        int so = rr * TROWB + c16 * 16;
        size_t g = qoff + (size_t)rr * DKK + c16 * 8;
        *reinterpret_cast<uint4*>(smem + SQ_HI + so) = *reinterpret_cast<const uint4*>(g_Qhi + g);
        *reinterpret_cast<uint4*>(smem + SQ_LO + so) = *reinterpret_cast<const uint4*>(g_Qlo + g);
    }

    float s[8][4];
    float c[8][4];
    float mA = -1e30f, mB = -1e30f, lA = 0.f, lB = 0.f;
#pragma unroll
    for (int di = 0; di < 8; di++)
#pragma unroll
        for (int e = 0; e < 4; e++) c[di][e] = 0.f;

    for (int kt = 0; kt < SEQ / 64; kt++) {
        __syncthreads();
        const size_t kb0 = kvoff + (size_t)kt * 64 * DKK;
#pragma unroll
        for (int i = 0; i < 2; i++) {
            int idx = tid + i * 256;
            int rr = idx >> 3, c16 = idx & 7;
            int so = rr * TROWB + c16 * 16;
            size_t g = kb0 + (size_t)rr * DKK + c16 * 8;
            *reinterpret_cast<uint4*>(smem + SK_HI_F + so) = *reinterpret_cast<const uint4*>(g_Khi + g);
            *reinterpret_cast<uint4*>(smem + SK_LO_F + so) = *reinterpret_cast<const uint4*>(g_Klo + g);
            *reinterpret_cast<uint4*>(smem + SV_HI_F + so) = *reinterpret_cast<const uint4*>(g_Vhi + g);
            *reinterpret_cast<uint4*>(smem + SV_LO_F + so) = *reinterpret_cast<const uint4*>(g_Vlo + g);
        }
        __syncthreads();

        // ---- S = Q K^T (scaled Q) ----
#pragma unroll
        for (int ni = 0; ni < 8; ni++)
#pragma unroll
            for (int e = 0; e < 4; e++) s[ni][e] = 0.f;

#pragma unroll
        for (int ks = 0; ks < 4; ks++) {
            const uint32_t kb = ks * 32;
            uint32_t ah[4], al[4];
            uint32_t qaddr = sb + SQ_HI + (uint32_t)(wq * 16 + lrow) * TROWB + kb + lhalf;
            ldsm4(ah[0], ah[1], ah[2], ah[3], qaddr);
            ldsm4(al[0], al[1], al[2], al[3], qaddr + (SQ_LO - SQ_HI));
#pragma unroll
            for (int g = 0; g < 4; g++) {
                uint32_t r0, r1, r2, r3;
                uint32_t kaddr = sb + SK_HI_F + (uint32_t)(g * 16 + lrow) * TROWB + kb + lhalf;
                ldsm4(r0, r1, r2, r3, kaddr);
                uint32_t bh0[2] = {r0, r2}, bh1[2] = {r1, r3};
                ldsm4(r0, r1, r2, r3, kaddr + (SK_LO_F - SK_HI_F));
                uint32_t bl0[2] = {r0, r2}, bl1[2] = {r1, r3};
                mma16816(s[2*g],   ah, bh0); mma16816(s[2*g],   ah, bl0); mma16816(s[2*g],   al, bh0);
                mma16816(s[2*g+1], ah, bh1); mma16816(s[2*g+1], ah, bl1); mma16816(s[2*g+1], al, bh1);
            }
        }

        // ---- online softmax (rows lr and lr+8; reduce over 4 lanes) ----
        float cA = s[0][0], cB = s[0][2];
#pragma unroll
        for (int ni = 0; ni < 8; ni++) {
            cA = fmaxf(cA, fmaxf(s[ni][0], s[ni][1]));
            cB = fmaxf(cB, fmaxf(s[ni][2], s[ni][3]));
        }
#pragma unroll
        for (int off = 1; off <= 2; off <<= 1) {
            cA = fmaxf(cA, __shfl_xor_sync(0xffffffffu, cA, off));
            cB = fmaxf(cB, __shfl_xor_sync(0xffffffffu, cB, off));
        }
        float nA = fmaxf(mA, cA), nB = fmaxf(mB, cB);
        float scA = __expf(mA - nA), scB = __expf(mB - nB);
        mA = nA; mB = nB;
        float lsA = 0.f, lsB = 0.f;
#pragma unroll
        for (int ni = 0; ni < 8; ni++) {
            s[ni][0] = __expf(s[ni][0] - mA); lsA += s[ni][0];
            s[ni][1] = __expf(s[ni][1] - mA); lsA += s[ni][1];
            s[ni][2] = __expf(s[ni][2] - mB); lsB += s[ni][2];
            s[ni][3] = __expf(s[ni][3] - mB); lsB += s[ni][3];
        }
#pragma unroll
        for (int off = 1; off <= 2; off <<= 1) {
            lsA += __shfl_xor_sync(0xffffffffu, lsA, off);
            lsB += __shfl_xor_sync(0xffffffffu, lsB, off);
        }
        lA = lA * scA + lsA;
        lB = lB * scB + lsB;
#pragma unroll
        for (int di = 0; di < 8; di++) {
            c[di][0] *= scA; c[di][1] *= scA;
            c[di][2] *= scB; c[di][3] *= scB;
        }

        // ---- O += P V  (P fragments from s registers, split hi/lo) ----
#pragma unroll
        for (int ks = 0; ks < 4; ks++) {
            uint32_t pa_hi[4], pa_lo[4];
            split2(s[2*ks][0],   s[2*ks][1],   pa_hi[0], pa_lo[0]);
            split2(s[2*ks][2],   s[2*ks][3],   pa_hi[1], pa_lo[1]);
            split2(s[2*ks+1][0], s[2*ks+1][1], pa_hi[2], pa_lo[2]);
            split2(s[2*ks+1][2], s[2*ks+1][3], pa_hi[3], pa_lo[3]);
#pragma unroll
            for (int g = 0; g < 4; g++) {
                uint32_t r0, r1, r2, r3;
                uint32_t vaddr = sb + SV_HI_F + (uint32_t)(ks * 16 + vrow) * TROWB
                               + (uint32_t)(g * 16 + vcol) * 2;
                ldsm4t(r0, r1, r2, r3, vaddr);
                uint32_t vh0[2] = {r0, r2}, vh1[2] = {r1, r3};
                ldsm4t(r0, r1, r2, r3, vaddr + (SV_LO_F - SV_HI_F));
                uint32_t vl0[2] = {r0, r2}, vl1[2] = {r1, r3};
                mma16816(c[2*g],   pa_hi, vh0); mma16816(c[2*g],   pa_hi, vl0); mma16816(c[2*g],   pa_lo, vh0);
                mma16816(c[2*g+1], pa_hi, vh1); mma16816(c[2*g+1], pa_hi, vl1); mma16816(c[2*g+1], pa_lo, vh1);
            }
        }
    }

    // ---- epilogue: context -> split bf16, token-major [T][1024] ----
    const float iA = 1.f / lA, iB = 1.f / lB;
    const int srowA = qb * 128 + wq * 16 + (lane >> 2);
    const size_t baseA = ((size_t)(b * SEQ + srowA)) * DMODEL + h * DKK + (lane & 3) * 2;
    const size_t baseB = baseA + (size_t)8 * DMODEL;
#pragma unroll
    for (int di = 0; di < 8; di++) {
        uint32_t hi, lo;
        split2(c[di][0] * iA, c[di][1] * iA, hi, lo);
        *reinterpret_cast<uint32_t*>(g_Chi + baseA + di * 8) = hi;
        *reinterpret_cast<uint32_t*>(g_Clo + baseA + di * 8) = lo;
        split2(c[di][2] * iB, c[di][3] * iB, hi, lo);
        *reinterpret_cast<uint32_t*>(g_Chi + baseB + di * 8) = hi;
        *reinterpret_cast<uint32_t*>(g_Clo + baseB + di * 8) = lo;
    }
}

// ---------------------------------------------------------------------------
extern "C" void kernel_launch(void* const* d_in, const int* in_sizes, int n_in,
                              void* d_out, int out_size)
{
    (void)in_sizes; (void)n_in; (void)out_size;
    const float* x  = (const float*)d_in[0];
    const float* wq = (const float*)d_in[1];
    const float* wk = (const float*)d_in[2];
    const float* wv = (const float*)d_in[3];
    const float* wo = (const float*)d_in[4];
    const float* bo = (const float*)d_in[5];
    float* out = (float*)d_out;

    cudaFuncSetAttribute(qkv_mma_kernel,     cudaFuncAttributeMaxDynamicSharedMemorySize, SM_TOTAL);
    cudaFuncSetAttribute(outproj_mma_kernel, cudaFuncAttributeMaxDynamicSharedMemorySize, SM_TOTAL);
    cudaFuncSetAttribute(flash_mma_kernel,   cudaFuncAttributeMaxDynamicSharedMemorySize, FSMEM);

    // 0) split-convert X and all weights to bf16 hi/lo
    cvt_kernel<<<dim3(4096, 5), 256>>>(x, wq, wk, wv, wo);

    // 1) QKV projections (HMMA), head-major split-bf16 outputs
    qkv_mma_kernel<<<dim3(NTOK / 128, DMODEL / 128, 3), 256, SM_TOTAL>>>();

    // 2) flash attention on HMMA, emits split-bf16 context
    flash_mma_kernel<<<dim3(SEQ / 128, NBATCH * NHEADS), 256, FSMEM>>>();

    // 3) output projection (HMMA) + bias
    outproj_mma_kernel<<<dim3(NTOK / 128, DMODEL / 128), 256, SM_TOTAL>>>(bo, out);
}